// round 1
// baseline (speedup 1.0000x reference)
#include <cuda_runtime.h>

// Scalar broadcast cell: cross_sum + linear bias, computed by kernel 1,
// consumed by kernel 2. __device__ global => no allocation.
__device__ float g_cross_plus_bias;

static constexpr int FEAS = 4096;
static constexpr int K    = 64;

// ---------------------------------------------------------------------------
// Kernel 1: reduce cross (FEAS x K) -> 0.5*(|colsum|^2 + |V|_F^2) + b0
// Single block, 256 threads. Thread t handles column k = t&63, row-stripe ty = t>>6.
// ---------------------------------------------------------------------------
__global__ void fm_cross_kernel(const float* __restrict__ cross,
                                const float* __restrict__ linear_b) {
    __shared__ float s_col[256];   // per-(ty,k) column partial sums
    __shared__ float s_diag[256];  // per-thread diag partials

    const int tid = threadIdx.x;
    const int k   = tid & (K - 1);
    const int ty  = tid >> 6;          // 0..3

    float col = 0.f, diag = 0.f;
    for (int f = ty; f < FEAS; f += 4) {
        float v = cross[f * K + k];    // warp reads 128B contiguous -> coalesced
        col  += v;
        diag += v * v;
    }
    s_col[tid]  = col;
    s_diag[tid] = diag;
    __syncthreads();

    // fold the 4 row-stripes per column; square the column sum
    if (tid < K) {
        float cs = s_col[tid] + s_col[tid + 64] + s_col[tid + 128] + s_col[tid + 192];
        s_col[tid] = cs * cs;
    }
    __syncthreads();

    if (tid < 32) {
        float t = s_col[tid] + s_col[tid + 32];           // 64 squared col sums
        float d = 0.f;
        #pragma unroll
        for (int i = 0; i < 8; i++) d += s_diag[tid + i * 32];  // 256 diag partials
        #pragma unroll
        for (int o = 16; o > 0; o >>= 1) {
            t += __shfl_down_sync(0xffffffffu, t, o);
            d += __shfl_down_sync(0xffffffffu, d, o);
        }
        if (tid == 0)
            g_cross_plus_bias = 0.5f * (t + d) + linear_b[0];
    }
}

// ---------------------------------------------------------------------------
// Kernel 2: one block per row. dot(x[row], w) + scalar -> sigmoid -> out[row].
// 256 threads, 4 float4 loads each (16 floats/thread). HBM-streaming.
// ---------------------------------------------------------------------------
__global__ __launch_bounds__(256, 8)
void fm_matvec_kernel(const float4* __restrict__ x,
                      const float4* __restrict__ w,
                      float* __restrict__ out) {
    const int row = blockIdx.x;
    const int tid = threadIdx.x;
    const float4* xr = x + (size_t)row * (FEAS / 4);

    float acc = 0.f;
    #pragma unroll
    for (int i = 0; i < 4; i++) {
        const int idx = tid + i * 256;
        float4 xv = xr[idx];
        float4 wv = __ldg(&w[idx]);    // 16KB, L2-resident across all rows
        acc += xv.x * wv.x + xv.y * wv.y + xv.z * wv.z + xv.w * wv.w;
    }

    // warp reduce
    #pragma unroll
    for (int o = 16; o > 0; o >>= 1)
        acc += __shfl_down_sync(0xffffffffu, acc, o);

    __shared__ float s_part[8];
    if ((tid & 31) == 0) s_part[tid >> 5] = acc;
    __syncthreads();

    if (tid == 0) {
        float total = 0.f;
        #pragma unroll
        for (int i = 0; i < 8; i++) total += s_part[i];
        float z = total + g_cross_plus_bias;
        out[row] = 1.f / (1.f + __expf(-z));
    }
}

extern "C" void kernel_launch(void* const* d_in, const int* in_sizes, int n_in,
                              void* d_out, int out_size) {
    const float* x        = (const float*)d_in[0];  // (B, FEAS)
    const float* cross    = (const float*)d_in[1];  // (FEAS, 1, K)
    const float* linear_w = (const float*)d_in[2];  // (1, FEAS)
    const float* linear_b = (const float*)d_in[3];  // (1,)
    float* out = (float*)d_out;                     // (B, 1)

    const int B = in_sizes[0] / FEAS;               // 4096

    fm_cross_kernel<<<1, 256>>>(cross, linear_b);
    fm_matvec_kernel<<<B, 256>>>((const float4*)x, (const float4*)linear_w, out);
}

// round 2
// speedup vs baseline: 2.9191x; 2.9191x over previous
#include <cuda_runtime.h>

static constexpr int FEAS = 4096;
static constexpr int K    = 64;
static constexpr int NCROSS_BLKS = 64;   // each reduces 64 rows of cross
static constexpr int ROWS_PER_BLK = 8;   // warp-per-row, 256 threads

// Persistent device state (zero-init at module load; every replay restores it).
__device__ float g_colsum[K];
__device__ float g_diag;
__device__ float g_scalar;        // 0.5*(|colsum|^2 + |V|_F^2) + bias
__device__ int   g_cross_count;   // arrival counter for cross blocks
__device__ int   g_done;          // release flag for matvec epilogue
__device__ int   g_mv_count;      // arrival counter for matvec blocks

__global__ __launch_bounds__(256, 8)
void fm_fused_kernel(const float4* __restrict__ x,
                     const float4* __restrict__ w,
                     const float*  __restrict__ cross,
                     const float*  __restrict__ linear_b,
                     float* __restrict__ out,
                     int n_mv_blocks) {
    const int tid  = threadIdx.x;
    const int lane = tid & 31;
    const int warp = tid >> 5;

    if (blockIdx.x < NCROSS_BLKS) {
        // ---------------- cross reduction slice: 64 rows x 64 cols ----------
        __shared__ float s_col[256];
        __shared__ float s_diag[256];
        __shared__ int   s_last;

        const int k    = tid & (K - 1);
        const int ty   = tid >> 6;                 // 0..3
        const int base = blockIdx.x * 64;

        float col = 0.f, diag = 0.f;
        #pragma unroll 4
        for (int f = base + ty; f < base + 64; f += 4) {
            float v = cross[f * K + k];            // coalesced 128B/warp
            col  += v;
            diag += v * v;
        }
        s_col[tid]  = col;
        s_diag[tid] = diag;
        __syncthreads();

        if (tid < K) {
            float cs = s_col[tid] + s_col[tid + 64] + s_col[tid + 128] + s_col[tid + 192];
            atomicAdd(&g_colsum[tid], cs);
        }
        if (warp == 0) {                           // reduce 256 diag partials
            float d = 0.f;
            #pragma unroll
            for (int i = 0; i < 8; i++) d += s_diag[lane + i * 32];
            #pragma unroll
            for (int o = 16; o > 0; o >>= 1) d += __shfl_down_sync(0xffffffffu, d, o);
            if (lane == 0) atomicAdd(&g_diag, d);
        }
        __threadfence();
        __syncthreads();

        if (tid == 0)
            s_last = (atomicAdd(&g_cross_count, 1) == NCROSS_BLKS - 1) ? 1 : 0;
        __syncthreads();

        if (s_last) {
            // finalize: scalar = 0.5*(sum cs^2 + diag) + b0 ; then reset state
            if (warp == 0) {
                float a = g_colsum[lane];
                float b = g_colsum[lane + 32];
                float t = a * a + b * b;
                #pragma unroll
                for (int o = 16; o > 0; o >>= 1) t += __shfl_down_sync(0xffffffffu, t, o);
                if (lane == 0) {
                    g_scalar = 0.5f * (t + g_diag) + linear_b[0];
                    __threadfence();
                    atomicExch(&g_done, 1);        // release
                }
            }
            __syncthreads();                        // reads of g_colsum done
            if (tid < K) g_colsum[tid] = 0.f;       // reset for next replay
            if (tid == 0) { g_diag = 0.f; g_cross_count = 0; }
        }
        return;
    }

    // ---------------- matvec: warp-per-row, 8 rows per block ----------------
    const int row = (blockIdx.x - NCROSS_BLKS) * ROWS_PER_BLK + warp;
    const float4* xr = x + (size_t)row * (FEAS / 4);

    float acc = 0.f;
    #pragma unroll 8
    for (int j = 0; j < FEAS / 4 / 32; j++) {      // 32 float4 per lane
        const int idx = lane + j * 32;
        float4 xv = xr[idx];
        float4 wv = __ldg(&w[idx]);                // 16KB, L1/L2-resident
        acc += xv.x * wv.x + xv.y * wv.y + xv.z * wv.z + xv.w * wv.w;
    }
    #pragma unroll
    for (int o = 16; o > 0; o >>= 1)
        acc += __shfl_down_sync(0xffffffffu, acc, o);

    if (lane == 0) {
        // wait for cross scalar (long ready by now: cross blocks launch first)
        while (*(volatile int*)&g_done == 0) __nanosleep(64);
        __threadfence();                           // acquire
        float z = acc + g_scalar;
        out[row] = 1.f / (1.f + __expf(-z));
    }
    __syncthreads();                               // all warps past the spin
    if (tid == 0) {
        if (atomicAdd(&g_mv_count, 1) == n_mv_blocks - 1) {
            g_done = 0;                            // reset for next replay
            g_mv_count = 0;
        }
    }
}

extern "C" void kernel_launch(void* const* d_in, const int* in_sizes, int n_in,
                              void* d_out, int out_size) {
    const float* x        = (const float*)d_in[0];  // (B, FEAS)
    const float* cross    = (const float*)d_in[1];  // (FEAS, 1, K)
    const float* linear_w = (const float*)d_in[2];  // (1, FEAS)
    const float* linear_b = (const float*)d_in[3];  // (1,)
    float* out = (float*)d_out;

    const int B = in_sizes[0] / FEAS;               // 4096
    const int n_mv = B / ROWS_PER_BLK;              // 512

    fm_fused_kernel<<<NCROSS_BLKS + n_mv, 256>>>(
        (const float4*)x, (const float4*)linear_w, cross, linear_b, out, n_mv);
}